// round 13
// baseline (speedup 1.0000x reference)
#include <cuda_runtime.h>

// ---------------------------------------------------------------------------
// AutoregressiveGRUWithAttention  (B=1024, L=64, T=128, IN=13, H=64, OUT=13)
//
// R12: fused 2-sync pipeline. Key algebra: gi(t) = Wih @ y(t-1)
//        = Wih @ (Wf·o(t-1) + bf) = (Wih@Wf)·o(t-1) + (Wih·bf)
// so with Wfusion = Wih@Wf precomputed per block, the whole decoder step is:
//   Phase A (all warps, 1 row/thread, weights in regs):
//       gh = Whh·h, gf = Wfusion·o, lg = Wa·o, y = Wf·o -> gmem
//   Phase B (512 threads = 8 batches x 64 channels):
//       fold (lg, o_prev) into online softmax, GRU gates, publish h/o.
// 512 threads x 128 blocks. 461 weight rows register-resident (64 regs each).
// Online-softmax attention == reference masked softmax (validated R7-R11).
// ---------------------------------------------------------------------------

typedef unsigned long long ull;

namespace {
constexpr int L_ = 64, T_ = 128, IN_ = 13, H_ = 64, OUT_ = 13, NB_ = 8;
constexpr int THREADS_ = 512, BLOCKS_ = 128;
constexpr int HS_ = 68;              // state plane row stride
constexpr int GP_ = NB_ * HS_;       // 544 floats per plane
constexpr int XT_ = 16, XPB_ = L_ * XT_;

constexpr int SM_SH  = 0;                  // h   [8][68]
constexpr int SM_SO  = SM_SH + GP_;        // o   [8][68]
constexpr int SM_GH  = SM_SO + GP_;        // Whh.h   [3][8][68]
constexpr int SM_GF  = SM_GH + 3 * GP_;    // Wfus.o / Wih.x  [3][8][68]
constexpr int SM_LG  = SM_GF + 3 * GP_;    // logits [8][68]
constexpr int SM_BFX = SM_LG + GP_;        // Wih.bf [192]
constexpr int SM_SX  = SM_BFX + 192;       // x [8][1024]
constexpr int SM_FLOATS = SM_SX + NB_ * XPB_;
constexpr int SMEM_BYTES = SM_FLOATS * 4;  // ~53.1 KB
}

__device__ __forceinline__ ull fma2_(ull a, ull b, ull c) {
    ull d;
    asm("fma.rn.f32x2 %0, %1, %2, %3;" : "=l"(d) : "l"(a), "l"(b), "l"(c));
    return d;
}
__device__ __forceinline__ float hsum2_(ull a) {
    unsigned lo, hi;
    asm("mov.b64 {%0, %1}, %2;" : "=r"(lo), "=r"(hi) : "l"(a));
    return __uint_as_float(lo) + __uint_as_float(hi);
}
__device__ __forceinline__ ull pack2_(float lo, float hi) {
    ull d;
    asm("mov.b64 %0, {%1, %2};" : "=l"(d) : "r"(__float_as_uint(lo)), "r"(__float_as_uint(hi)));
    return d;
}
__device__ __forceinline__ float sigmoid_(float a) {
    return __fdividef(1.f, 1.f + __expf(-a));
}
__device__ __forceinline__ float tanh_(float a) {
    float c  = fminf(fmaxf(a, -15.f), 15.f);
    float e2 = __expf(2.f * c);
    return __fdividef(e2 - 1.f, e2 + 1.f);
}

// One 64-wide register row dotted with 8 state vectors (smem broadcasts).
__device__ __forceinline__ void dots8_(const ull (&w2)[32], const float* src,
                                       float (&r8)[8]) {
    #pragma unroll
    for (int b2 = 0; b2 < 4; ++b2) {
        const float* pa = src + (2 * b2) * HS_;
        const float* pb = src + (2 * b2 + 1) * HS_;
        ull aa = 0, ab = 0;
        #pragma unroll
        for (int c = 0; c < 16; ++c) {
            ulonglong2 va = *(const ulonglong2*)(pa + 4 * c);
            ulonglong2 vb = *(const ulonglong2*)(pb + 4 * c);
            aa = fma2_(w2[2*c], va.x, aa); aa = fma2_(w2[2*c+1], va.y, aa);
            ab = fma2_(w2[2*c], vb.x, ab); ab = fma2_(w2[2*c+1], vb.y, ab);
        }
        r8[2 * b2]     = hsum2_(aa);
        r8[2 * b2 + 1] = hsum2_(ab);
    }
}

// Encoder input dots: padded-16 Wih row (regs) . x_t  for 8 batches.
__device__ __forceinline__ void gidots8_(const ull (&wi2)[8], const float* sx_t,
                                         float (&r8)[8]) {
    #pragma unroll
    for (int b = 0; b < 8; ++b) {
        const ulonglong2* v = (const ulonglong2*)(sx_t + b * XPB_);
        ull acc = 0;
        #pragma unroll
        for (int c = 0; c < 4; ++c) {
            ulonglong2 vv = v[c];
            acc = fma2_(wi2[2*c], vv.x, acc);
            acc = fma2_(wi2[2*c+1], vv.y, acc);
        }
        r8[b] = hsum2_(acc);
    }
}

__global__ void __launch_bounds__(THREADS_, 1)
gru_attn_kernel(const float* __restrict__ x, const int* __restrict__ lengths,
                const float* __restrict__ Wih, const float* __restrict__ Whh,
                const float* __restrict__ bih, const float* __restrict__ bhh,
                const float* __restrict__ Wf,  const float* __restrict__ bf,
                const float* __restrict__ Wa,  const float* __restrict__ ba,
                float* __restrict__ out)
{
    extern __shared__ float sm[];
    float* sh   = sm + SM_SH;
    float* so   = sm + SM_SO;
    float* gh   = sm + SM_GH;
    float* gf   = sm + SM_GF;
    float* slg  = sm + SM_LG;
    float* sbfx = sm + SM_BFX;
    float* sx   = sm + SM_SX;
    __shared__ int smax;

    const int tid = threadIdx.x;
    const int b0  = blockIdx.x * NB_;
    // Phase-B ownership: one (batch, channel) per thread
    const int j2  = tid & 63;
    const int bb  = tid >> 6;
    const int off = bb * HS_ + j2;

    // ---- stage x, zero h
    for (int idx = tid; idx < NB_ * XPB_; idx += THREADS_) {
        int b = idx >> 10, r = idx & 1023, tt = r >> 4, i = r & 15;
        sx[idx] = (i < IN_) ? x[(size_t)(b0 + b) * (L_ * IN_) + tt * IN_ + i] : 0.f;
    }
    for (int idx = tid; idx < GP_; idx += THREADS_) sh[idx] = 0.f;
    if (tid == 0) {
        int m = 0;
        #pragma unroll
        for (int b = 0; b < NB_; ++b) m = max(m, lengths[b0 + b]);
        smax = m;
    }

    // ---- per-role weight rows (register resident)
    ull w2[32];     // 64-wide row: Whh | Wfusion | Wa | Wf
    ull wi2[8];     // Wih row (padded to 16), threads 192-383 only
    float bf_reg = 0.f;

    if (tid < 192) {
        const ull* p = (const ull*)(Whh + tid * H_);
        #pragma unroll
        for (int k = 0; k < 32; ++k) w2[k] = p[k];
    } else if (tid < 384) {
        const int r2 = tid - 192;
        float wih[13];
        #pragma unroll
        for (int i = 0; i < IN_; ++i) wih[i] = Wih[r2 * IN_ + i];
        // bfx[r2] = Wih row . bf
        float bx = 0.f;
        #pragma unroll
        for (int i = 0; i < IN_; ++i) bx += wih[i] * bf[i];
        sbfx[r2] = bx;
        // Wfusion row: Wfusion[r2][c] = sum_i Wih[r2][i] * Wf[i][c]
        #pragma unroll
        for (int k = 0; k < 32; ++k) {
            float a0 = 0.f, a1 = 0.f;
            #pragma unroll
            for (int i = 0; i < IN_; ++i) {
                a0 += wih[i] * Wf[i * H_ + 2 * k];
                a1 += wih[i] * Wf[i * H_ + 2 * k + 1];
            }
            w2[k] = pack2_(a0, a1);
        }
        // padded Wih row for encoder gi
        #pragma unroll
        for (int k = 0; k < 8; ++k) {
            float a0 = (2 * k     < IN_) ? wih[2 * k]     : 0.f;
            float a1 = (2 * k + 1 < IN_) ? wih[2 * k + 1] : 0.f;
            wi2[k] = pack2_(a0, a1);
        }
    } else if (tid < 448) {
        const ull* p = (const ull*)(Wa + (tid - 384) * H_);
        #pragma unroll
        for (int k = 0; k < 32; ++k) w2[k] = p[k];
    } else if (tid < 448 + OUT_) {
        const ull* p = (const ull*)(Wf + (tid - 448) * H_);
        #pragma unroll
        for (int k = 0; k < 32; ++k) w2[k] = p[k];
        bf_reg = bf[tid - 448];
    }

    // ---- per-thread Phase-B constants
    const float brr = bih[j2]          + bhh[j2];
    const float bzz = bih[H_ + j2]     + bhh[H_ + j2];
    const float bni = bih[2 * H_ + j2];
    const float bnh = bhh[2 * H_ + j2];
    const float bav = ba[j2];
    const int   len = lengths[b0 + bb];

    __syncthreads();
    const int Lmax = smax;
    const float bfxr = sbfx[j2];
    const float bfxz = sbfx[H_ + j2];
    const float bfxn = sbfx[2 * H_ + j2];

    float h_own = 0.f;

    // =======================  ENCODER  =======================
    for (int t = 0; t < Lmax; ++t) {
        // Phase A: gh = Whh.h (threads 0-191), gi = Wih.x_t (threads 192-383)
        if (tid < 192) {
            float r8[8]; dots8_(w2, sh, r8);
            float* dst = gh + (tid >> 6) * GP_;
            const int jd = tid & 63;
            #pragma unroll
            for (int b = 0; b < 8; ++b) dst[b * HS_ + jd] = r8[b];
        } else if (tid < 384) {
            float r8[8]; gidots8_(wi2, sx + t * XT_, r8);
            const int r2 = tid - 192;
            float* dst = gf + (r2 >> 6) * GP_;
            const int jd = r2 & 63;
            #pragma unroll
            for (int b = 0; b < 8; ++b) dst[b * HS_ + jd] = r8[b];
        }
        __syncthreads();
        // Phase B: masked GRU update
        {
            float r = sigmoid_(gh[off] + gf[off] + brr);
            float z = sigmoid_(gh[GP_ + off] + gf[GP_ + off] + bzz);
            float n = tanh_((gf[2 * GP_ + off] + bni) + r * (gh[2 * GP_ + off] + bnh));
            float hne = (1.f - z) * n + z * h_own;
            h_own = (t < len) ? hne : h_own;
            sh[off] = h_own;
        }
        __syncthreads();
    }

    // o_init = outs[-1]: nonzero only when length == L (then equals final h)
    so[off] = (len == L_) ? h_own : 0.f;
    __syncthreads();

    // =======================  DECODER  =======================
    float m = -1e30f, s = 0.f, a = 0.f, o_prev = 0.f;

    for (int t = 0; t <= T_; ++t) {
        // ---- Phase A on state (h(t-1), o(t-1))
        if (tid < 192) {
            float r8[8]; dots8_(w2, sh, r8);
            float* dst = gh + (tid >> 6) * GP_;
            const int jd = tid & 63;
            #pragma unroll
            for (int b = 0; b < 8; ++b) dst[b * HS_ + jd] = r8[b];
        } else if (tid < 384) {
            float r8[8]; dots8_(w2, so, r8);
            const int r2 = tid - 192;
            float* dst = gf + (r2 >> 6) * GP_;
            const int jd = r2 & 63;
            #pragma unroll
            for (int b = 0; b < 8; ++b) dst[b * HS_ + jd] = r8[b];
        } else if (tid < 448) {
            float r8[8]; dots8_(w2, so, r8);
            const int jd = tid - 384;
            #pragma unroll
            for (int b = 0; b < 8; ++b) slg[b * HS_ + jd] = r8[b];
        } else if (tid < 448 + OUT_) {
            float r8[8]; dots8_(w2, so, r8);   // y(t-1) = Wf.o(t-1) + bf
            if (t > 0) {
                const int oc = tid - 448;
                #pragma unroll
                for (int b = 0; b < 8; ++b)
                    out[((size_t)(b0 + b) * T_ + (t - 1)) * OUT_ + oc] = r8[b] + bf_reg;
            }
        }
        __syncthreads();

        // ---- Phase B
        if (t < T_) {
            float l = slg[off] + bav;           // logit of o(t-1)
            if (t > 0) {                        // fold buf[t-1] = o(t-1)
                float mn = fmaxf(m, l);
                float c = __expf(m - mn), e = __expf(l - mn);
                s = s * c + e;  a = a * c + e * o_prev;  m = mn;
            }
            float r = sigmoid_(gh[off] + gf[off] + brr + bfxr);
            float z = sigmoid_(gh[GP_ + off] + gf[GP_ + off] + bzz + bfxz);
            float n = tanh_((gf[2 * GP_ + off] + bni + bfxn) +
                            r * (gh[2 * GP_ + off] + bnh));
            float hne = (1.f - z) * n + z * h_own;
            float att = (t == 0) ? 0.f : __fdividef(a, s);
            float ov  = hne + att;
            h_own  = hne;
            o_prev = ov;
            sh[off] = hne;
            so[off] = ov;
        }
        __syncthreads();
    }
}

extern "C" void kernel_launch(void* const* d_in, const int* in_sizes, int n_in,
                              void* d_out, int out_size) {
    const float* xp   = nullptr;
    const int*   lenp = nullptr;
    const float *Wihp = nullptr, *Whhp = nullptr, *bihp = nullptr, *bhhp = nullptr;
    const float *Wfp = nullptr, *bfp = nullptr, *Wap = nullptr, *bap = nullptr;

    for (int i = 0; i < n_in; ++i) {
        switch (in_sizes[i]) {
            case 1024 * 64 * 13: xp   = (const float*)d_in[i]; break;
            case 1024:           lenp = (const int*)d_in[i];   break;
            case 192 * 13:       Wihp = (const float*)d_in[i]; break;
            case 192 * 64:       Whhp = (const float*)d_in[i]; break;
            case 192:
                if (!bihp) bihp = (const float*)d_in[i];
                else       bhhp = (const float*)d_in[i];
                break;
            case 13 * 64:        Wfp  = (const float*)d_in[i]; break;
            case 13:             bfp  = (const float*)d_in[i]; break;
            case 64 * 64:        Wap  = (const float*)d_in[i]; break;
            case 64:             bap  = (const float*)d_in[i]; break;
            default: break;   // output_length scalar -> T=128 hardcoded
        }
    }

    cudaFuncSetAttribute(gru_attn_kernel,
                         cudaFuncAttributeMaxDynamicSharedMemorySize, SMEM_BYTES);

    gru_attn_kernel<<<BLOCKS_, THREADS_, SMEM_BYTES>>>(
        xp, lenp, Wihp, Whhp, bihp, bhhp, Wfp, bfp, Wap, bap, (float*)d_out);
}

// round 14
// speedup vs baseline: 1.2310x; 1.2310x over previous
#include <cuda_runtime.h>

// ---------------------------------------------------------------------------
// AutoregressiveGRUWithAttention  (B=1024, L=64, T=128, IN=13, H=64, OUT=13)
//
// R13 = R12's 2-sync fused pipeline (gi = Wfusion.o + bfx, Wfusion = Wih@Wf)
// with register-budget-aware layout: 256 threads (=> 256 regs/thread budget),
// TWO same-source weight rows per thread (128 weight regs), halving the
// smem-broadcast LDS traffic that bound R12 (L1=65%).
//   Phase A roles (decoder):  tid 0-95: Whh rows (t, t+96) on h
//                             tid 96-191: Wfusion rows (t-96, t) on o
//                             tid 192-223: Wa rows (k, k+32) on o
//                             tid 224-236: Wf row on o -> y -> gmem
//   Phase B: 256 threads x 2 (b,j) pairs: fold online softmax, GRU gates,
//            publish h/o. Encoder gi (Wih.x_t) is computed one step ahead in
//            phase B into registers (smem Wih at stride 17, conflict-free).
// Online-softmax attention == reference masked softmax (validated R7-R12).
// ---------------------------------------------------------------------------

typedef unsigned long long ull;

namespace {
constexpr int L_ = 64, T_ = 128, IN_ = 13, H_ = 64, OUT_ = 13, NB_ = 8;
constexpr int THREADS_ = 256, BLOCKS_ = 128;
constexpr int HS_ = 68;              // state row stride (16B-aligned rows)
constexpr int GP_ = NB_ * HS_;       // 544 floats per gate plane
constexpr int XT_ = 16, XPB_ = L_ * XT_;   // 1024 floats x-stage per batch
constexpr int WIHS_ = 17;            // Wih smem stride (odd -> conflict-free)

constexpr int SM_SH  = 0;                   // h   [8][68]
constexpr int SM_SO  = SM_SH  + GP_;        // o   [8][68]
constexpr int SM_GH  = SM_SO  + GP_;        // Whh.h  [3][8][68]
constexpr int SM_GF  = SM_GH  + 3 * GP_;    // Wfus.o [3][8][68]
constexpr int SM_LG  = SM_GF  + 3 * GP_;    // logits [8][68]
constexpr int SM_BFX = SM_LG  + GP_;        // Wih.bf [192]
constexpr int SM_WIH = SM_BFX + 192;        // [192][17]
constexpr int SM_SX  = SM_WIH + 192 * WIHS_ + 15; // pad to 16B; x [8][1024]
constexpr int SM_FLOATS = SM_SX + NB_ * XPB_;
constexpr int SMEM_BYTES = SM_FLOATS * 4;   // ~66.3 KB
}

__device__ __forceinline__ ull fma2_(ull a, ull b, ull c) {
    ull d;
    asm("fma.rn.f32x2 %0, %1, %2, %3;" : "=l"(d) : "l"(a), "l"(b), "l"(c));
    return d;
}
__device__ __forceinline__ float hsum2_(ull a) {
    unsigned lo, hi;
    asm("mov.b64 {%0, %1}, %2;" : "=r"(lo), "=r"(hi) : "l"(a));
    return __uint_as_float(lo) + __uint_as_float(hi);
}
__device__ __forceinline__ ull pack2_(float lo, float hi) {
    ull d;
    asm("mov.b64 %0, {%1, %2};" : "=l"(d) : "r"(__float_as_uint(lo)), "r"(__float_as_uint(hi)));
    return d;
}
__device__ __forceinline__ float sigmoid_(float a) {
    return __fdividef(1.f, 1.f + __expf(-a));
}
__device__ __forceinline__ float tanh_(float a) {
    float c  = fminf(fmaxf(a, -15.f), 15.f);
    float e2 = __expf(2.f * c);
    return __fdividef(e2 - 1.f, e2 + 1.f);
}

// Two register rows (w[0..31], w[32..63]) dotted with 8 state vectors.
// Chunk loads shared by both rows; 4 accumulator chains for ILP.
// Results written to dA[b*HS_], dB[b*HS_].
__device__ __forceinline__ void dots8_r2(const ull (&w)[64], const float* src,
                                         float* dA, float* dB) {
    #pragma unroll
    for (int b = 0; b < 8; b += 2) {
        const float* p0 = src + b * HS_;
        const float* p1 = src + (b + 1) * HS_;
        ull a0 = 0, a1 = 0, c0 = 0, c1 = 0;
        #pragma unroll
        for (int c = 0; c < 16; ++c) {
            ulonglong2 v0 = *(const ulonglong2*)(p0 + 4 * c);
            ulonglong2 v1 = *(const ulonglong2*)(p1 + 4 * c);
            a0 = fma2_(w[2*c],      v0.x, a0); a0 = fma2_(w[2*c+1],      v0.y, a0);
            a1 = fma2_(w[2*c],      v1.x, a1); a1 = fma2_(w[2*c+1],      v1.y, a1);
            c0 = fma2_(w[32+2*c],   v0.x, c0); c0 = fma2_(w[32+2*c+1],   v0.y, c0);
            c1 = fma2_(w[32+2*c],   v1.x, c1); c1 = fma2_(w[32+2*c+1],   v1.y, c1);
        }
        dA[b * HS_]       = hsum2_(a0);
        dA[(b + 1) * HS_] = hsum2_(a1);
        dB[b * HS_]       = hsum2_(c0);
        dB[(b + 1) * HS_] = hsum2_(c1);
    }
}

// One register row dotted with 8 state vectors -> y8.
__device__ __forceinline__ void dots8_r1(const ull* w, const float* src,
                                         float (&y8)[8]) {
    #pragma unroll
    for (int b = 0; b < 8; b += 2) {
        const float* p0 = src + b * HS_;
        const float* p1 = src + (b + 1) * HS_;
        ull a0 = 0, a1 = 0;
        #pragma unroll
        for (int c = 0; c < 16; ++c) {
            ulonglong2 v0 = *(const ulonglong2*)(p0 + 4 * c);
            ulonglong2 v1 = *(const ulonglong2*)(p1 + 4 * c);
            a0 = fma2_(w[2*c], v0.x, a0); a0 = fma2_(w[2*c+1], v0.y, a0);
            a1 = fma2_(w[2*c], v1.x, a1); a1 = fma2_(w[2*c+1], v1.y, a1);
        }
        y8[b]     = hsum2_(a0);
        y8[b + 1] = hsum2_(a1);
    }
}

__global__ void __launch_bounds__(THREADS_, 1)
gru_attn_kernel(const float* __restrict__ x, const int* __restrict__ lengths,
                const float* __restrict__ Wih, const float* __restrict__ Whh,
                const float* __restrict__ bih, const float* __restrict__ bhh,
                const float* __restrict__ Wf,  const float* __restrict__ bf,
                const float* __restrict__ Wa,  const float* __restrict__ ba,
                float* __restrict__ out)
{
    extern __shared__ float sm[];
    float* sh   = sm + SM_SH;
    float* so   = sm + SM_SO;
    float* gh   = sm + SM_GH;
    float* gf   = sm + SM_GF;
    float* slg  = sm + SM_LG;
    float* sbfx = sm + SM_BFX;
    float* sWih = sm + SM_WIH;
    float* sx   = sm + SM_SX;
    __shared__ int smax;

    const int tid = threadIdx.x;
    const int b0  = blockIdx.x * NB_;
    // Phase-B ownership: pairs (bb, j) and (bb+4, j)
    const int j2   = tid & 63;
    const int bb   = tid >> 6;
    const int off0 = bb * HS_ + j2;
    const int off1 = (bb + 4) * HS_ + j2;

    // ---- prologue staging
    for (int idx = tid; idx < NB_ * XPB_; idx += THREADS_) {
        int b = idx >> 10, r = idx & 1023, tt = r >> 4, i = r & 15;
        sx[idx] = (i < IN_) ? x[(size_t)(b0 + b) * (L_ * IN_) + tt * IN_ + i] : 0.f;
    }
    for (int idx = tid; idx < 192 * IN_; idx += THREADS_) {
        int r = idx / IN_, i = idx - r * IN_;
        sWih[r * WIHS_ + i] = Wih[idx];
    }
    for (int idx = tid; idx < GP_; idx += THREADS_) sh[idx] = 0.f;
    if (tid == 0) {
        int m = 0;
        #pragma unroll
        for (int b = 0; b < NB_; ++b) m = max(m, lengths[b0 + b]);
        smax = m;
    }

    // ---- per-role register rows + dst pointers
    ull w2[64];
    float bf_reg = 0.f;
    float* dA = gh;   // defaults, overwritten per role
    float* dB = gh;

    if (tid < 96) {                       // Whh rows (tid, tid+96), src = sh
        const ull* p = (const ull*)(Whh + tid * H_);
        #pragma unroll
        for (int k = 0; k < 32; ++k) w2[k] = p[k];
        p = (const ull*)(Whh + (tid + 96) * H_);
        #pragma unroll
        for (int k = 0; k < 32; ++k) w2[32 + k] = p[k];
        dA = gh + (tid >> 6) * GP_ + (tid & 63);
        dB = gh + ((tid + 96) >> 6) * GP_ + ((tid + 96) & 63);
    } else if (tid < 192) {               // Wfusion rows (tid-96, tid), src = so
        const int r0 = tid - 96, r1 = tid;
        float wA[13], wB[13];
        #pragma unroll
        for (int i = 0; i < IN_; ++i) { wA[i] = Wih[r0 * IN_ + i]; wB[i] = Wih[r1 * IN_ + i]; }
        float bxA = 0.f, bxB = 0.f;
        #pragma unroll
        for (int i = 0; i < IN_; ++i) { bxA += wA[i] * bf[i]; bxB += wB[i] * bf[i]; }
        sbfx[r0] = bxA; sbfx[r1] = bxB;
        #pragma unroll
        for (int k = 0; k < 32; ++k) {
            float a0 = 0.f, a1 = 0.f, b0v = 0.f, b1v = 0.f;
            #pragma unroll
            for (int i = 0; i < IN_; ++i) {
                float f0 = Wf[i * H_ + 2 * k], f1 = Wf[i * H_ + 2 * k + 1];
                a0  += wA[i] * f0;  a1  += wA[i] * f1;
                b0v += wB[i] * f0;  b1v += wB[i] * f1;
            }
            w2[k]      = pack2_(a0, a1);
            w2[32 + k] = pack2_(b0v, b1v);
        }
        dA = gf + (r0 >> 6) * GP_ + (r0 & 63);
        dB = gf + (r1 >> 6) * GP_ + (r1 & 63);
    } else if (tid < 224) {               // Wa rows (k, k+32), src = so
        const int r0 = tid - 192;
        const ull* p = (const ull*)(Wa + r0 * H_);
        #pragma unroll
        for (int k = 0; k < 32; ++k) w2[k] = p[k];
        p = (const ull*)(Wa + (r0 + 32) * H_);
        #pragma unroll
        for (int k = 0; k < 32; ++k) w2[32 + k] = p[k];
        dA = slg + r0;
        dB = slg + r0 + 32;
    } else {                              // Wf row (tid-224 clamped), src = so
        const int oc = min(tid - 224, OUT_ - 1);
        const ull* p = (const ull*)(Wf + oc * H_);
        #pragma unroll
        for (int k = 0; k < 32; ++k) { w2[k] = p[k]; w2[32 + k] = 0; }
        bf_reg = bf[oc];
    }
    const bool wf_ok = (tid >= 224) && (tid - 224 < OUT_);
    const int  wf_oc = tid - 224;

    // ---- Phase-B constants
    const float brr = bih[j2]          + bhh[j2];
    const float bzz = bih[H_ + j2]     + bhh[H_ + j2];
    const float bni = bih[2 * H_ + j2];
    const float bnh = bhh[2 * H_ + j2];
    const float bav = ba[j2];
    const int   len0 = lengths[b0 + bb];
    const int   len1 = lengths[b0 + bb + 4];

    __syncthreads();
    const int Lmax = smax;
    const float bfxr = sbfx[j2];
    const float bfxz = sbfx[H_ + j2];
    const float bfxn = sbfx[2 * H_ + j2];

    float h_own0 = 0.f, h_own1 = 0.f;
    float gr0, gz0, gn0, gr1, gz1, gn1;   // pipelined encoder gi

    // compute gi (Wih . x[tt]) for this thread's two (b,j) pairs
    auto compute_gi = [&](int tt) {
        float r0 = 0.f, z0 = 0.f, n0 = 0.f, r1 = 0.f, z1 = 0.f, n1 = 0.f;
        const float* xa = sx + bb * XPB_ + tt * XT_;
        const float* xb = sx + (bb + 4) * XPB_ + tt * XT_;
        #pragma unroll
        for (int i = 0; i < IN_; ++i) {
            float wr = sWih[j2 * WIHS_ + i];
            float wz = sWih[(64 + j2) * WIHS_ + i];
            float wn = sWih[(128 + j2) * WIHS_ + i];
            float va = xa[i], vb = xb[i];
            r0 += wr * va; z0 += wz * va; n0 += wn * va;
            r1 += wr * vb; z1 += wz * vb; n1 += wn * vb;
        }
        gr0 = r0; gz0 = z0; gn0 = n0; gr1 = r1; gz1 = z1; gn1 = n1;
    };
    compute_gi(0);

    // =======================  ENCODER  =======================
    for (int t = 0; t < Lmax; ++t) {
        // Phase A: Whh.h only (threads 0-95)
        if (tid < 96) dots8_r2(w2, sh, dA, dB);
        __syncthreads();
        // Phase B: gates with pipelined gi; masked update; prefetch gi(t+1)
        {
            float r = sigmoid_(gh[off0] + gr0 + brr);
            float z = sigmoid_(gh[GP_ + off0] + gz0 + bzz);
            float n = tanh_((gn0 + bni) + r * (gh[2 * GP_ + off0] + bnh));
            float hne = (1.f - z) * n + z * h_own0;
            h_own0 = (t < len0) ? hne : h_own0;
            sh[off0] = h_own0;
        }
        {
            float r = sigmoid_(gh[off1] + gr1 + brr);
            float z = sigmoid_(gh[GP_ + off1] + gz1 + bzz);
            float n = tanh_((gn1 + bni) + r * (gh[2 * GP_ + off1] + bnh));
            float hne = (1.f - z) * n + z * h_own1;
            h_own1 = (t < len1) ? hne : h_own1;
            sh[off1] = h_own1;
        }
        compute_gi((t + 1 < Lmax) ? (t + 1) : t);
        __syncthreads();
    }

    // o_init = outs[-1]: nonzero only when length == L (then equals final h)
    so[off0] = (len0 == L_) ? h_own0 : 0.f;
    so[off1] = (len1 == L_) ? h_own1 : 0.f;
    __syncthreads();

    // =======================  DECODER  =======================
    float m0 = -1e30f, s0 = 0.f, a0 = 0.f, op0 = 0.f;
    float m1 = -1e30f, s1 = 0.f, a1 = 0.f, op1 = 0.f;

    for (int t = 0; t <= T_; ++t) {
        // ---- Phase A on (h(t-1), o(t-1))
        if (tid < 96) {
            dots8_r2(w2, sh, dA, dB);
        } else if (tid < 224) {
            dots8_r2(w2, so, dA, dB);      // Wfusion -> gf, Wa -> slg
        } else {
            float y8[8];
            dots8_r1(w2, so, y8);           // y(t-1) = Wf.o(t-1) + bf
            if (t > 0 && wf_ok) {
                #pragma unroll
                for (int b = 0; b < 8; ++b)
                    out[((size_t)(b0 + b) * T_ + (t - 1)) * OUT_ + wf_oc] =
                        y8[b] + bf_reg;
            }
        }
        __syncthreads();

        // ---- Phase B
        if (t < T_) {
            {   // pair 0
                float l = slg[off0] + bav;
                if (t > 0) {
                    float mn = fmaxf(m0, l);
                    float c = __expf(m0 - mn), e = __expf(l - mn);
                    s0 = s0 * c + e;  a0 = a0 * c + e * op0;  m0 = mn;
                }
                float r = sigmoid_(gh[off0] + gf[off0] + brr + bfxr);
                float z = sigmoid_(gh[GP_ + off0] + gf[GP_ + off0] + bzz + bfxz);
                float n = tanh_((gf[2 * GP_ + off0] + bni + bfxn) +
                                r * (gh[2 * GP_ + off0] + bnh));
                float hne = (1.f - z) * n + z * h_own0;
                float att = (t == 0) ? 0.f : __fdividef(a0, s0);
                float ov = hne + att;
                h_own0 = hne;  op0 = ov;
                sh[off0] = hne;  so[off0] = ov;
            }
            {   // pair 1
                float l = slg[off1] + bav;
                if (t > 0) {
                    float mn = fmaxf(m1, l);
                    float c = __expf(m1 - mn), e = __expf(l - mn);
                    s1 = s1 * c + e;  a1 = a1 * c + e * op1;  m1 = mn;
                }
                float r = sigmoid_(gh[off1] + gf[off1] + brr + bfxr);
                float z = sigmoid_(gh[GP_ + off1] + gf[GP_ + off1] + bzz + bfxz);
                float n = tanh_((gf[2 * GP_ + off1] + bni + bfxn) +
                                r * (gh[2 * GP_ + off1] + bnh));
                float hne = (1.f - z) * n + z * h_own1;
                float att = (t == 0) ? 0.f : __fdividef(a1, s1);
                float ov = hne + att;
                h_own1 = hne;  op1 = ov;
                sh[off1] = hne;  so[off1] = ov;
            }
        }
        __syncthreads();
    }
}

extern "C" void kernel_launch(void* const* d_in, const int* in_sizes, int n_in,
                              void* d_out, int out_size) {
    const float* xp   = nullptr;
    const int*   lenp = nullptr;
    const float *Wihp = nullptr, *Whhp = nullptr, *bihp = nullptr, *bhhp = nullptr;
    const float *Wfp = nullptr, *bfp = nullptr, *Wap = nullptr, *bap = nullptr;

    for (int i = 0; i < n_in; ++i) {
        switch (in_sizes[i]) {
            case 1024 * 64 * 13: xp   = (const float*)d_in[i]; break;
            case 1024:           lenp = (const int*)d_in[i];   break;
            case 192 * 13:       Wihp = (const float*)d_in[i]; break;
            case 192 * 64:       Whhp = (const float*)d_in[i]; break;
            case 192:
                if (!bihp) bihp = (const float*)d_in[i];
                else       bhhp = (const float*)d_in[i];
                break;
            case 13 * 64:        Wfp  = (const float*)d_in[i]; break;
            case 13:             bfp  = (const float*)d_in[i]; break;
            case 64 * 64:        Wap  = (const float*)d_in[i]; break;
            case 64:             bap  = (const float*)d_in[i]; break;
            default: break;   // output_length scalar -> T=128 hardcoded
        }
    }

    cudaFuncSetAttribute(gru_attn_kernel,
                         cudaFuncAttributeMaxDynamicSharedMemorySize, SMEM_BYTES);

    gru_attn_kernel<<<BLOCKS_, THREADS_, SMEM_BYTES>>>(
        xp, lenp, Wihp, Whhp, bihp, bhhp, Wfp, bfp, Wap, bap, (float*)d_out);
}